// round 4
// baseline (speedup 1.0000x reference)
#include <cuda_runtime.h>
#include <cuda_bf16.h>
#include <cstdint>

#define FDIM 1024
#define BATCH 8
#define SEQ 2048
#define MTOT (BATCH * SEQ)   // 16384

// ---------------- scratch (__device__ globals; no allocation allowed) ----------------
__device__ __nv_bfloat16 g_xh[MTOT * FDIM], g_xl[MTOT * FDIM];
__device__ __nv_bfloat16 g_Wh[3][FDIM * FDIM], g_Wl[3][FDIM * FDIM];
__device__ __nv_bfloat16 g_Qh[MTOT * FDIM], g_Ql[MTOT * FDIM];
__device__ __nv_bfloat16 g_Kh[MTOT * FDIM], g_Kl[MTOT * FDIM];
__device__ __nv_bfloat16 g_Vh[MTOT * FDIM], g_Vl[MTOT * FDIM];
__device__ __nv_bfloat16 g_Vth[BATCH * FDIM * SEQ], g_Vtl[BATCH * FDIM * SEQ];
__device__ float g_S[(size_t)BATCH * SEQ * SEQ];
__device__ __nv_bfloat16 g_Ph[(size_t)BATCH * SEQ * SEQ], g_Pl[(size_t)BATCH * SEQ * SEQ];

// ---------------- PTX helpers ----------------
__device__ __forceinline__ uint32_t smem_to_u32(const void* p) {
    uint32_t a;
    asm("{ .reg .u64 t; cvta.to.shared.u64 t, %1; cvt.u32.u64 %0, t; }" : "=r"(a) : "l"(p));
    return a;
}
__device__ __forceinline__ void cp_async16(uint32_t dst, const void* src) {
    asm volatile("cp.async.cg.shared.global [%0], [%1], 16;" :: "r"(dst), "l"(src));
}
#define CP_COMMIT() asm volatile("cp.async.commit_group;" ::: "memory")
#define CP_WAIT0()  asm volatile("cp.async.wait_group 0;" ::: "memory")
#define CP_WAIT1()  asm volatile("cp.async.wait_group 1;" ::: "memory")

__device__ __forceinline__ void ldm4(uint32_t (&r)[4], uint32_t addr) {
    asm volatile("ldmatrix.sync.aligned.m8n8.x4.shared.b16 {%0,%1,%2,%3}, [%4];"
                 : "=r"(r[0]), "=r"(r[1]), "=r"(r[2]), "=r"(r[3]) : "r"(addr));
}
__device__ __forceinline__ void mma16816(float (&d)[4], const uint32_t (&a)[4],
                                         uint32_t b0, uint32_t b1) {
    asm volatile("mma.sync.aligned.m16n8k16.row.col.f32.bf16.bf16.f32 "
                 "{%0,%1,%2,%3}, {%4,%5,%6,%7}, {%8,%9}, {%0,%1,%2,%3};"
                 : "+f"(d[0]), "+f"(d[1]), "+f"(d[2]), "+f"(d[3])
                 : "r"(a[0]), "r"(a[1]), "r"(a[2]), "r"(a[3]), "r"(b0), "r"(b1));
}

// ---------------- GEMM config ----------------
// CTA tile 256(m) x 128(n), BK=32, 8 warps as 4(m) x 2(n), warp tile 64x64.
// SMEM stage: Ah(256 rows), Al(256), Bh(128), Bl(128); rows padded to 80 B.
#define ROWPAD   80
#define A_T_B    (256 * ROWPAD)   // 20480
#define B_T_B    (128 * ROWPAD)   // 10240
#define STAGE_B  (2 * A_T_B + 2 * B_T_B)   // 61440
#define NSTAGE   3
#define SMEM_SZ  (NSTAGE * STAGE_B)        // 184320

__device__ __forceinline__ void load_chunk(
    uint32_t stage_base, int tid,
    const __nv_bfloat16* Ah, const __nv_bfloat16* Al,
    const __nv_bfloat16* Bh, const __nv_bfloat16* Bl,
    long long kofs, int Kd)
{
    // A tiles: 256 rows x 4 segs = 1024 cp / tile
    #pragma unroll
    for (int i = 0; i < 4; i++) {
        int u = tid + i * 256;
        int row = u >> 2, seg = u & 3;
        cp_async16(stage_base + row * ROWPAD + seg * 16,
                   Ah + (long long)row * Kd + kofs + seg * 8);
        cp_async16(stage_base + A_T_B + row * ROWPAD + seg * 16,
                   Al + (long long)row * Kd + kofs + seg * 8);
    }
    // B tiles: 128 rows x 4 segs = 512 cp / tile
    #pragma unroll
    for (int i = 0; i < 2; i++) {
        int u = tid + i * 256;
        int row = u >> 2, seg = u & 3;
        cp_async16(stage_base + 2 * A_T_B + row * ROWPAD + seg * 16,
                   Bh + (long long)row * Kd + kofs + seg * 8);
        cp_async16(stage_base + 2 * A_T_B + B_T_B + row * ROWPAD + seg * 16,
                   Bl + (long long)row * Kd + kofs + seg * 8);
    }
    CP_COMMIT();
}

// C(MxN) = alpha * A(MxK) @ B(NxK)^T [+ bias]; split-bf16 3-term HMMA.
// mode 0: outHi/outLo bf16 (+bias). else: outF fp32.
__global__ __launch_bounds__(256, 1) void gemm_mma(
    const __nv_bfloat16* __restrict__ Ahi, const __nv_bfloat16* __restrict__ Alo,
    const __nv_bfloat16* __restrict__ Bhi, const __nv_bfloat16* __restrict__ Blo,
    const float* __restrict__ bias,
    __nv_bfloat16* __restrict__ outHi, __nv_bfloat16* __restrict__ outLo,
    float* __restrict__ outF,
    int N, int Kd, float alpha, int mode,
    long long sA, long long sB, long long sC)
{
    extern __shared__ char smem[];
    const uint32_t smem0 = smem_to_u32(smem);
    const int tid = threadIdx.x;
    const int wid = tid >> 5;
    const int lane = tid & 31;
    const int z = blockIdx.z;
    const long long row0 = (long long)blockIdx.x * 256;
    const long long col0 = (long long)blockIdx.y * 128;

    const __nv_bfloat16* Ah = Ahi + (long long)z * sA + row0 * Kd;
    const __nv_bfloat16* Al = Alo + (long long)z * sA + row0 * Kd;
    const __nv_bfloat16* Bh = Bhi + (long long)z * sB + col0 * Kd;
    const __nv_bfloat16* Bl = Blo + (long long)z * sB + col0 * Kd;

    const int warp_m0 = (wid >> 1) * 64;   // 0,64,128,192
    const int warp_n0 = (wid & 1) * 64;    // 0,64

    const uint32_t lmofs = (uint32_t)(lane & 15) * ROWPAD + (uint32_t)(lane >> 4) * 16;

    float acc[4][8][4];
    #pragma unroll
    for (int a = 0; a < 4; a++)
        #pragma unroll
        for (int b = 0; b < 8; b++)
            #pragma unroll
            for (int cI = 0; cI < 4; cI++) acc[a][b][cI] = 0.0f;

    const int NC = Kd >> 5;   // BK = 32

    load_chunk(smem0, tid, Ah, Al, Bh, Bl, 0, Kd);
    load_chunk(smem0 + STAGE_B, tid, Ah, Al, Bh, Bl, 32, Kd);

    int stage = 0;
    for (int c = 0; c < NC; c++) {
        if (c + 1 < NC) CP_WAIT1(); else CP_WAIT0();
        __syncthreads();   // single barrier: stage `stage` ready; prior reads done

        const uint32_t st = smem0 + stage * STAGE_B;
        const uint32_t tAh = st, tAl = st + A_T_B;
        const uint32_t tBh = st + 2 * A_T_B, tBl = st + 2 * A_T_B + B_T_B;

        #pragma unroll
        for (int ks = 0; ks < 2; ks++) {
            uint32_t ah[4][4], al[4][4], bh[4][4], bl[4][4];
            #pragma unroll
            for (int g = 0; g < 4; g++) {
                uint32_t oa = (uint32_t)(warp_m0 + g * 16) * ROWPAD + ks * 32 + lmofs;
                ldm4(ah[g], tAh + oa);
                ldm4(al[g], tAl + oa);
                uint32_t ob = (uint32_t)(warp_n0 + g * 16) * ROWPAD + ks * 32 + lmofs;
                ldm4(bh[g], tBh + ob);
                ldm4(bl[g], tBl + ob);
            }
            // term-major: acc reuse distance = 32 MMAs
            #pragma unroll
            for (int mf = 0; mf < 4; mf++)
                #pragma unroll
                for (int g = 0; g < 4; g++)
                    #pragma unroll
                    for (int p = 0; p < 2; p++)
                        mma16816(acc[mf][g * 2 + p], ah[mf], bh[g][p], bh[g][p + 2]);
            #pragma unroll
            for (int mf = 0; mf < 4; mf++)
                #pragma unroll
                for (int g = 0; g < 4; g++)
                    #pragma unroll
                    for (int p = 0; p < 2; p++)
                        mma16816(acc[mf][g * 2 + p], ah[mf], bl[g][p], bl[g][p + 2]);
            #pragma unroll
            for (int mf = 0; mf < 4; mf++)
                #pragma unroll
                for (int g = 0; g < 4; g++)
                    #pragma unroll
                    for (int p = 0; p < 2; p++)
                        mma16816(acc[mf][g * 2 + p], al[mf], bh[g][p], bh[g][p + 2]);
        }

        if (c + 2 < NC) {
            int ns = stage + 2; if (ns >= NSTAGE) ns -= NSTAGE;
            load_chunk(smem0 + ns * STAGE_B, tid, Ah, Al, Bh, Bl,
                       (long long)(c + 2) * 32, Kd);
        }
        if (++stage == NSTAGE) stage = 0;
    }

    // ---- epilogue: fragments -> gmem ----
    const int rbase = warp_m0 + (lane >> 2);
    const int cbase = warp_n0 + 2 * (lane & 3);
    #pragma unroll
    for (int mf = 0; mf < 4; mf++) {
        #pragma unroll
        for (int nf = 0; nf < 8; nf++) {
            #pragma unroll
            for (int h = 0; h < 2; h++) {
                long long r = row0 + rbase + mf * 16 + h * 8;
                long long cc = col0 + cbase + nf * 8;
                float f0 = acc[mf][nf][h * 2 + 0] * alpha;
                float f1 = acc[mf][nf][h * 2 + 1] * alpha;
                if (mode == 0) {
                    f0 += bias[cc];
                    f1 += bias[cc + 1];
                    __nv_bfloat16 h0 = __float2bfloat16(f0);
                    __nv_bfloat16 l0 = __float2bfloat16(f0 - __bfloat162float(h0));
                    __nv_bfloat16 h1 = __float2bfloat16(f1);
                    __nv_bfloat16 l1 = __float2bfloat16(f1 - __bfloat162float(h1));
                    long long o = r * (long long)N + cc;
                    __nv_bfloat162 ph; ph.x = h0; ph.y = h1;
                    __nv_bfloat162 pl; pl.x = l0; pl.y = l1;
                    *(__nv_bfloat162*)(outHi + o) = ph;
                    *(__nv_bfloat162*)(outLo + o) = pl;
                } else {
                    long long o = (long long)z * sC + r * (long long)N + cc;
                    *(float2*)(outF + o) = make_float2(f0, f1);
                }
            }
        }
    }
}

// split fp32 -> (hi, lo) bf16
__global__ __launch_bounds__(256) void split_f32(
    const float* __restrict__ src, __nv_bfloat16* __restrict__ hi,
    __nv_bfloat16* __restrict__ lo, int n)
{
    int i = (blockIdx.x * 256 + threadIdx.x) * 4;
    if (i >= n) return;
    float4 v = *(const float4*)(src + i);
    float f[4] = { v.x, v.y, v.z, v.w };
    __nv_bfloat16 h[4], l[4];
    #pragma unroll
    for (int k = 0; k < 4; k++) {
        h[k] = __float2bfloat16(f[k]);
        l[k] = __float2bfloat16(f[k] - __bfloat162float(h[k]));
    }
    __nv_bfloat162 h0; h0.x = h[0]; h0.y = h[1];
    __nv_bfloat162 h1; h1.x = h[2]; h1.y = h[3];
    __nv_bfloat162 l0; l0.x = l[0]; l0.y = l[1];
    __nv_bfloat162 l1; l1.x = l[2]; l1.y = l[3];
    *(__nv_bfloat162*)(hi + i) = h0; *(__nv_bfloat162*)(hi + i + 2) = h1;
    *(__nv_bfloat162*)(lo + i) = l0; *(__nv_bfloat162*)(lo + i + 2) = l1;
}

// Vt[b][d][s] = V[b*SEQ+s][d]
__global__ __launch_bounds__(256) void transpose_v(
    const __nv_bfloat16* __restrict__ Vh, const __nv_bfloat16* __restrict__ Vl,
    __nv_bfloat16* __restrict__ Vth, __nv_bfloat16* __restrict__ Vtl)
{
    __shared__ __nv_bfloat16 th[32][33], tl[32][33];
    const int b = blockIdx.z;
    const int s0 = blockIdx.x * 32, d0 = blockIdx.y * 32;
    const int tx = threadIdx.x, ty = threadIdx.y;
    #pragma unroll
    for (int j = 0; j < 4; j++) {
        int r = ty + j * 8;
        long long src = (long long)(b * SEQ + s0 + r) * FDIM + d0 + tx;
        th[r][tx] = Vh[src];
        tl[r][tx] = Vl[src];
    }
    __syncthreads();
    #pragma unroll
    for (int j = 0; j < 4; j++) {
        int r = ty + j * 8;
        long long dst = (long long)(b * FDIM + d0 + r) * SEQ + s0 + tx;
        Vth[dst] = th[tx][r];
        Vtl[dst] = tl[tx][r];
    }
}

// row softmax: S fp32 -> P hi/lo bf16
__global__ __launch_bounds__(256) void softmax_rows(
    const float* __restrict__ S, __nv_bfloat16* __restrict__ Ph,
    __nv_bfloat16* __restrict__ Pl)
{
    __shared__ float red[256];
    const long long roff = (long long)blockIdx.x * SEQ;
    const float* p = S + roff;
    const int tid = threadIdx.x;

    float v[8];
    float mx = -1e30f;
    #pragma unroll
    for (int i = 0; i < 8; i++) { v[i] = p[tid + i * 256]; mx = fmaxf(mx, v[i]); }
    red[tid] = mx;
    __syncthreads();
    for (int s = 128; s > 0; s >>= 1) {
        if (tid < s) red[tid] = fmaxf(red[tid], red[tid + s]);
        __syncthreads();
    }
    mx = red[0];
    __syncthreads();

    float sum = 0.0f;
    #pragma unroll
    for (int i = 0; i < 8; i++) { v[i] = __expf(v[i] - mx); sum += v[i]; }
    red[tid] = sum;
    __syncthreads();
    for (int s = 128; s > 0; s >>= 1) {
        if (tid < s) red[tid] += red[tid + s];
        __syncthreads();
    }
    float inv = 1.0f / red[0];

    #pragma unroll
    for (int i = 0; i < 8; i++) {
        float w = v[i] * inv;
        __nv_bfloat16 h = __float2bfloat16(w);
        __nv_bfloat16 l = __float2bfloat16(w - __bfloat162float(h));
        Ph[roff + tid + i * 256] = h;
        Pl[roff + tid + i * 256] = l;
    }
}

extern "C" void kernel_launch(void* const* d_in, const int* in_sizes, int n_in,
                              void* d_out, int out_size)
{
    const float* x  = (const float*)d_in[0];
    const float* Wq = (const float*)d_in[1];
    const float* bq = (const float*)d_in[2];
    const float* Wk = (const float*)d_in[3];
    const float* bk = (const float*)d_in[4];
    const float* Wv = (const float*)d_in[5];
    const float* bv = (const float*)d_in[6];
    float* out = (float*)d_out;

    cudaFuncSetAttribute(gemm_mma, cudaFuncAttributeMaxDynamicSharedMemorySize, SMEM_SZ);

    __nv_bfloat16 *xh, *xl, *Wh, *Wl, *Qh, *Ql, *Kh, *Kl, *Vh, *Vl, *Vth, *Vtl, *Ph, *Pl;
    float* S;
    cudaGetSymbolAddress((void**)&xh, g_xh);   cudaGetSymbolAddress((void**)&xl, g_xl);
    cudaGetSymbolAddress((void**)&Wh, g_Wh);   cudaGetSymbolAddress((void**)&Wl, g_Wl);
    cudaGetSymbolAddress((void**)&Qh, g_Qh);   cudaGetSymbolAddress((void**)&Ql, g_Ql);
    cudaGetSymbolAddress((void**)&Kh, g_Kh);   cudaGetSymbolAddress((void**)&Kl, g_Kl);
    cudaGetSymbolAddress((void**)&Vh, g_Vh);   cudaGetSymbolAddress((void**)&Vl, g_Vl);
    cudaGetSymbolAddress((void**)&Vth, g_Vth); cudaGetSymbolAddress((void**)&Vtl, g_Vtl);
    cudaGetSymbolAddress((void**)&Ph, g_Ph);   cudaGetSymbolAddress((void**)&Pl, g_Pl);
    cudaGetSymbolAddress((void**)&S, g_S);

    const int NX = MTOT * FDIM;
    const int NW = FDIM * FDIM;
    const long long WSZ = (long long)FDIM * FDIM;

    split_f32<<<NX / 4 / 256, 256>>>(x, xh, xl, NX);
    split_f32<<<NW / 4 / 256, 256>>>(Wq, Wh + 0 * WSZ, Wl + 0 * WSZ, NW);
    split_f32<<<NW / 4 / 256, 256>>>(Wk, Wh + 1 * WSZ, Wl + 1 * WSZ, NW);
    split_f32<<<NW / 4 / 256, 256>>>(Wv, Wh + 2 * WSZ, Wl + 2 * WSZ, NW);

    // QKV projections: M=16384, N=1024, K=1024
    dim3 g1(MTOT / 256, FDIM / 128, 1);
    gemm_mma<<<g1, 256, SMEM_SZ>>>(xh, xl, Wh + 0 * WSZ, Wl + 0 * WSZ, bq, Qh, Ql, nullptr,
                                   FDIM, FDIM, 1.0f, 0, 0, 0, 0);
    gemm_mma<<<g1, 256, SMEM_SZ>>>(xh, xl, Wh + 1 * WSZ, Wl + 1 * WSZ, bk, Kh, Kl, nullptr,
                                   FDIM, FDIM, 1.0f, 0, 0, 0, 0);
    gemm_mma<<<g1, 256, SMEM_SZ>>>(xh, xl, Wh + 2 * WSZ, Wl + 2 * WSZ, bv, Vh, Vl, nullptr,
                                   FDIM, FDIM, 1.0f, 0, 0, 0, 0);

    // scores = Q @ K^T / 32
    dim3 g2(SEQ / 256, SEQ / 128, BATCH);
    gemm_mma<<<g2, 256, SMEM_SZ>>>(Qh, Ql, Kh, Kl, nullptr, nullptr, nullptr, S,
                                   SEQ, FDIM, 0.03125f, 1,
                                   (long long)SEQ * FDIM, (long long)SEQ * FDIM,
                                   (long long)SEQ * SEQ);

    transpose_v<<<dim3(SEQ / 32, FDIM / 32, BATCH), dim3(32, 8)>>>(Vh, Vl, Vth, Vtl);

    softmax_rows<<<BATCH * SEQ, 256>>>(S, Ph, Pl);

    // out = P @ Vt^T : M=2048, N=1024, K=2048
    dim3 g3(SEQ / 256, FDIM / 128, BATCH);
    gemm_mma<<<g3, 256, SMEM_SZ>>>(Ph, Pl, Vth, Vtl, nullptr, nullptr, nullptr, out,
                                   FDIM, SEQ, 1.0f, 2,
                                   (long long)SEQ * SEQ, (long long)FDIM * SEQ,
                                   (long long)SEQ * FDIM);
}

// round 6
// speedup vs baseline: 1.2539x; 1.2539x over previous
#include <cuda_runtime.h>
#include <cuda_fp16.h>
#include <cstdint>

#define FDIM 1024
#define BATCH 8
#define SEQ 2048
#define MTOT (BATCH * SEQ)   // 16384

#define LO_SCALE   1024.0f
#define INV_LO     (1.0f / 1024.0f)

// ---------------- scratch (__device__ globals) ----------------
__device__ __half g_xh[MTOT * FDIM], g_xl[MTOT * FDIM];
__device__ __half g_Wh[3][FDIM * FDIM], g_Wl[3][FDIM * FDIM];
__device__ __half g_Qh[MTOT * FDIM], g_Ql[MTOT * FDIM];
__device__ __half g_Kh[MTOT * FDIM];
__device__ __half g_Vh[MTOT * FDIM];
__device__ __half g_Vth[BATCH * FDIM * SEQ];
__device__ float  g_S[(size_t)BATCH * SEQ * SEQ];
__device__ __half g_Ph[(size_t)BATCH * SEQ * SEQ], g_Pl[(size_t)BATCH * SEQ * SEQ];

// ---------------- PTX helpers ----------------
__device__ __forceinline__ uint32_t smem_to_u32(const void* p) {
    uint32_t a;
    asm("{ .reg .u64 t; cvta.to.shared.u64 t, %1; cvt.u32.u64 %0, t; }" : "=r"(a) : "l"(p));
    return a;
}
__device__ __forceinline__ void cp_async16(uint32_t dst, const void* src) {
    asm volatile("cp.async.cg.shared.global [%0], [%1], 16;" :: "r"(dst), "l"(src));
}
#define CP_COMMIT() asm volatile("cp.async.commit_group;" ::: "memory")
#define CP_WAIT0()  asm volatile("cp.async.wait_group 0;" ::: "memory")
#define CP_WAIT1()  asm volatile("cp.async.wait_group 1;" ::: "memory")

__device__ __forceinline__ void ldm4(uint32_t (&r)[4], uint32_t addr) {
    asm volatile("ldmatrix.sync.aligned.m8n8.x4.shared.b16 {%0,%1,%2,%3}, [%4];"
                 : "=r"(r[0]), "=r"(r[1]), "=r"(r[2]), "=r"(r[3]) : "r"(addr));
}
// fp32-accum fp16 MMA
__device__ __forceinline__ void mma_f32(float (&d)[4], const uint32_t (&a)[4],
                                        uint32_t b0, uint32_t b1) {
    asm volatile("mma.sync.aligned.m16n8k16.row.col.f32.f16.f16.f32 "
                 "{%0,%1,%2,%3}, {%4,%5,%6,%7}, {%8,%9}, {%0,%1,%2,%3};"
                 : "+f"(d[0]), "+f"(d[1]), "+f"(d[2]), "+f"(d[3])
                 : "r"(a[0]), "r"(a[1]), "r"(a[2]), "r"(a[3]), "r"(b0), "r"(b1));
}
// fp16-accum fp16 MMA (correction terms)
__device__ __forceinline__ void mma_f16(uint32_t (&d)[2], const uint32_t (&a)[4],
                                        uint32_t b0, uint32_t b1) {
    asm volatile("mma.sync.aligned.m16n8k16.row.col.f16.f16.f16.f16 "
                 "{%0,%1}, {%2,%3,%4,%5}, {%6,%7}, {%0,%1};"
                 : "+r"(d[0]), "+r"(d[1])
                 : "r"(a[0]), "r"(a[1]), "r"(a[2]), "r"(a[3]), "r"(b0), "r"(b1));
}

// ---------------- GEMM config ----------------
// CTA 128(m) x 128(n), BK=32, 8 warps (2m x 4n), warp tile 64x32.
// SMEM stage: Ah, Al, Bh, Bl tiles, 128 rows x 32 fp16 (64 B) padded to 80 B.
#define ROWPAD   80
#define TILE_B   (128 * ROWPAD)            // 10240
#define STAGE_B  (4 * TILE_B)              // 40960
#define NSTAGE   3
#define SMEM_SZ  (NSTAGE * STAGE_B)        // 122880

// terms==3: load Ah,Al,Bh,Bl. terms==2: skip Bl.
__device__ __forceinline__ void load_chunk(
    uint32_t st, int tid,
    const __half* Ah, const __half* Al, const __half* Bh, const __half* Bl,
    long long kofs, int Kd, int terms)
{
    #pragma unroll
    for (int i = 0; i < 2; i++) {
        int u = tid + i * 256;
        int row = u >> 2, seg = u & 3;
        long long go = (long long)row * Kd + kofs + seg * 8;
        uint32_t so = row * ROWPAD + seg * 16;
        cp_async16(st + so,              Ah + go);
        cp_async16(st + TILE_B + so,     Al + go);
        cp_async16(st + 2 * TILE_B + so, Bh + go);
        if (terms == 3) cp_async16(st + 3 * TILE_B + so, Bl + go);
    }
    CP_COMMIT();
}

// C(MxN) = alpha*(A @ B^T) [+bias].  A = Ah + Al/1024, B = Bh + Bl/1024.
// terms 3: hh(f32) + [h*bl + al*bh](f16).  terms 2: hh(f32) + [al*bh](f16).
// omode 0: half hi+lo out (+bias). 1: half hi out (+bias). 2: fp32 out.
__global__ __launch_bounds__(256, 1) void gemm_mma(
    const __half* __restrict__ Ahi, const __half* __restrict__ Alo,
    const __half* __restrict__ Bhi, const __half* __restrict__ Blo,
    const float* __restrict__ bias,
    __half* __restrict__ outHi, __half* __restrict__ outLo,
    float* __restrict__ outF,
    int N, int Kd, float alpha, int terms, int omode,
    long long sA, long long sB, long long sC)
{
    extern __shared__ char smem[];
    const uint32_t smem0 = smem_to_u32(smem);
    const int tid = threadIdx.x;
    const int wid = tid >> 5;
    const int lane = tid & 31;
    const int z = blockIdx.z;
    const long long row0 = (long long)blockIdx.x * 128;
    const long long col0 = (long long)blockIdx.y * 128;

    const __half* Ah = Ahi + (long long)z * sA + row0 * Kd;
    const __half* Al = Alo + (long long)z * sA + row0 * Kd;
    const __half* Bh = Bhi + (long long)z * sB + col0 * Kd;
    const __half* Bl = (terms == 3) ? (Blo + (long long)z * sB + col0 * Kd) : Bh;

    const int warp_m0 = (wid >> 2) * 64;   // 0,64
    const int warp_n0 = (wid & 3) * 32;    // 0,32,64,96

    const uint32_t lmofs = (uint32_t)(lane & 15) * ROWPAD + (uint32_t)(lane >> 4) * 16;

    float acc[4][4][4];
    uint32_t accH[4][4][2];
    #pragma unroll
    for (int a = 0; a < 4; a++)
        #pragma unroll
        for (int b = 0; b < 4; b++) {
            accH[a][b][0] = 0u; accH[a][b][1] = 0u;
            #pragma unroll
            for (int cI = 0; cI < 4; cI++) acc[a][b][cI] = 0.0f;
        }

    const int NC = Kd >> 5;   // BK=32

    load_chunk(smem0, tid, Ah, Al, Bh, Bl, 0, Kd, terms);
    load_chunk(smem0 + STAGE_B, tid, Ah, Al, Bh, Bl, 32, Kd, terms);

    int stage = 0;
    for (int c = 0; c < NC; c++) {
        if (c + 1 < NC) CP_WAIT1(); else CP_WAIT0();
        __syncthreads();

        const uint32_t st = smem0 + stage * STAGE_B;
        const uint32_t tAh = st, tAl = st + TILE_B;
        const uint32_t tBh = st + 2 * TILE_B, tBl = st + 3 * TILE_B;

        #pragma unroll
        for (int ks = 0; ks < 2; ks++) {
            uint32_t ah[4][4], al[4][4], bh[2][4], bl[2][4];
            #pragma unroll
            for (int g = 0; g < 4; g++) {
                uint32_t oa = (uint32_t)(warp_m0 + g * 16) * ROWPAD + ks * 32 + lmofs;
                ldm4(ah[g], tAh + oa);
                ldm4(al[g], tAl + oa);
            }
            #pragma unroll
            for (int g = 0; g < 2; g++) {
                uint32_t ob = (uint32_t)(warp_n0 + g * 16) * ROWPAD + ks * 32 + lmofs;
                ldm4(bh[g], tBh + ob);
                if (terms == 3) ldm4(bl[g], tBl + ob);
            }
            // main product: Ah * Bh  (fp32 accum)
            #pragma unroll
            for (int mf = 0; mf < 4; mf++)
                #pragma unroll
                for (int g = 0; g < 2; g++)
                    #pragma unroll
                    for (int p = 0; p < 2; p++)
                        mma_f32(acc[mf][g * 2 + p], ah[mf], bh[g][p], bh[g][p + 2]);
            // correction: Al' * Bh  (f16 accum; Al pre-scaled x1024)
            #pragma unroll
            for (int mf = 0; mf < 4; mf++)
                #pragma unroll
                for (int g = 0; g < 2; g++)
                    #pragma unroll
                    for (int p = 0; p < 2; p++)
                        mma_f16(accH[mf][g * 2 + p], al[mf], bh[g][p], bh[g][p + 2]);
            // correction: Ah * Bl'  (3-term only)
            if (terms == 3) {
                #pragma unroll
                for (int mf = 0; mf < 4; mf++)
                    #pragma unroll
                    for (int g = 0; g < 2; g++)
                        #pragma unroll
                        for (int p = 0; p < 2; p++)
                            mma_f16(accH[mf][g * 2 + p], ah[mf], bl[g][p], bl[g][p + 2]);
            }
        }

        if (c + 2 < NC) {
            int ns = stage + 2; if (ns >= NSTAGE) ns -= NSTAGE;
            load_chunk(smem0 + ns * STAGE_B, tid, Ah, Al, Bh, Bl,
                       (long long)(c + 2) * 32, Kd, terms);
        }
        if (++stage == NSTAGE) stage = 0;
    }

    // ---- epilogue ----
    const int rbase = warp_m0 + (lane >> 2);
    const int cbase = warp_n0 + 2 * (lane & 3);
    #pragma unroll
    for (int mf = 0; mf < 4; mf++) {
        #pragma unroll
        for (int nf = 0; nf < 4; nf++) {
            #pragma unroll
            for (int h = 0; h < 2; h++) {
                long long r = row0 + rbase + mf * 16 + h * 8;
                long long cc = col0 + cbase + nf * 8;
                __half2 ch = *reinterpret_cast<const __half2*>(&accH[mf][nf][h]);
                float2 cf = __half22float2(ch);
                float f0 = (acc[mf][nf][h * 2 + 0] + cf.x * INV_LO) * alpha;
                float f1 = (acc[mf][nf][h * 2 + 1] + cf.y * INV_LO) * alpha;
                if (omode <= 1) {
                    f0 += bias[cc];
                    f1 += bias[cc + 1];
                    __half h0 = __float2half(f0);
                    __half h1 = __float2half(f1);
                    long long o = r * (long long)N + cc;
                    __half2 ph; ph.x = h0; ph.y = h1;
                    *(__half2*)(outHi + o) = ph;
                    if (omode == 0) {
                        __half2 pl;
                        pl.x = __float2half((f0 - __half2float(h0)) * LO_SCALE);
                        pl.y = __float2half((f1 - __half2float(h1)) * LO_SCALE);
                        *(__half2*)(outLo + o) = pl;
                    }
                } else {
                    long long o = (long long)z * sC + r * (long long)N + cc;
                    *(float2*)(outF + o) = make_float2(f0, f1);
                }
            }
        }
    }
}

// split fp32 -> (hi, lo*1024) fp16
__global__ __launch_bounds__(256) void split_f32(
    const float* __restrict__ src, __half* __restrict__ hi,
    __half* __restrict__ lo, int n)
{
    int i = (blockIdx.x * 256 + threadIdx.x) * 4;
    if (i >= n) return;
    float4 v = *(const float4*)(src + i);
    float f[4] = { v.x, v.y, v.z, v.w };
    __half h[4], l[4];
    #pragma unroll
    for (int k = 0; k < 4; k++) {
        h[k] = __float2half(f[k]);
        l[k] = __float2half((f[k] - __half2float(h[k])) * LO_SCALE);
    }
    __half2 h0; h0.x = h[0]; h0.y = h[1];
    __half2 h1; h1.x = h[2]; h1.y = h[3];
    __half2 l0; l0.x = l[0]; l0.y = l[1];
    __half2 l1; l1.x = l[2]; l1.y = l[3];
    *(__half2*)(hi + i) = h0; *(__half2*)(hi + i + 2) = h1;
    *(__half2*)(lo + i) = l0; *(__half2*)(lo + i + 2) = l1;
}

// Vt[b][d][s] = V[b*SEQ+s][d]  (hi only)
__global__ __launch_bounds__(256) void transpose_v(
    const __half* __restrict__ Vh, __half* __restrict__ Vth)
{
    __shared__ __half th[32][33];
    const int b = blockIdx.z;
    const int s0 = blockIdx.x * 32, d0 = blockIdx.y * 32;
    const int tx = threadIdx.x, ty = threadIdx.y;
    #pragma unroll
    for (int j = 0; j < 4; j++) {
        int r = ty + j * 8;
        th[r][tx] = Vh[(long long)(b * SEQ + s0 + r) * FDIM + d0 + tx];
    }
    __syncthreads();
    #pragma unroll
    for (int j = 0; j < 4; j++) {
        int r = ty + j * 8;
        Vth[(long long)(b * FDIM + d0 + r) * SEQ + s0 + tx] = th[tx][r];
    }
}

// row softmax: S fp32 -> P hi + lo*1024 fp16
__global__ __launch_bounds__(256) void softmax_rows(
    const float* __restrict__ S, __half* __restrict__ Ph, __half* __restrict__ Pl)
{
    __shared__ float red[256];
    const long long roff = (long long)blockIdx.x * SEQ;
    const float* p = S + roff;
    const int tid = threadIdx.x;

    float v[8];
    float mx = -1e30f;
    #pragma unroll
    for (int i = 0; i < 8; i++) { v[i] = p[tid + i * 256]; mx = fmaxf(mx, v[i]); }
    red[tid] = mx;
    __syncthreads();
    for (int s = 128; s > 0; s >>= 1) {
        if (tid < s) red[tid] = fmaxf(red[tid], red[tid + s]);
        __syncthreads();
    }
    mx = red[0];
    __syncthreads();

    float sum = 0.0f;
    #pragma unroll
    for (int i = 0; i < 8; i++) { v[i] = __expf(v[i] - mx); sum += v[i]; }
    red[tid] = sum;
    __syncthreads();
    for (int s = 128; s > 0; s >>= 1) {
        if (tid < s) red[tid] += red[tid + s];
        __syncthreads();
    }
    float inv = 1.0f / red[0];

    #pragma unroll
    for (int i = 0; i < 8; i++) {
        float w = v[i] * inv;
        __half h = __float2half(w);
        Ph[roff + tid + i * 256] = h;
        Pl[roff + tid + i * 256] = __float2half((w - __half2float(h)) * LO_SCALE);
    }
}

extern "C" void kernel_launch(void* const* d_in, const int* in_sizes, int n_in,
                              void* d_out, int out_size)
{
    const float* x  = (const float*)d_in[0];
    const float* Wq = (const float*)d_in[1];
    const float* bq = (const float*)d_in[2];
    const float* Wk = (const float*)d_in[3];
    const float* bk = (const float*)d_in[4];
    const float* Wv = (const float*)d_in[5];
    const float* bv = (const float*)d_in[6];
    float* out = (float*)d_out;

    cudaFuncSetAttribute(gemm_mma, cudaFuncAttributeMaxDynamicSharedMemorySize, SMEM_SZ);

    __half *xh, *xl, *Wh, *Wl, *Qh, *Ql, *Kh, *Vh, *Vth, *Ph, *Pl;
    float* S;
    cudaGetSymbolAddress((void**)&xh, g_xh);   cudaGetSymbolAddress((void**)&xl, g_xl);
    cudaGetSymbolAddress((void**)&Wh, g_Wh);   cudaGetSymbolAddress((void**)&Wl, g_Wl);
    cudaGetSymbolAddress((void**)&Qh, g_Qh);   cudaGetSymbolAddress((void**)&Ql, g_Ql);
    cudaGetSymbolAddress((void**)&Kh, g_Kh);
    cudaGetSymbolAddress((void**)&Vh, g_Vh);
    cudaGetSymbolAddress((void**)&Vth, g_Vth);
    cudaGetSymbolAddress((void**)&Ph, g_Ph);   cudaGetSymbolAddress((void**)&Pl, g_Pl);
    cudaGetSymbolAddress((void**)&S, g_S);

    const int NX = MTOT * FDIM;
    const int NW = FDIM * FDIM;
    const long long WSZ = (long long)FDIM * FDIM;

    split_f32<<<NX / 4 / 256, 256>>>(x, xh, xl, NX);
    split_f32<<<NW / 4 / 256, 256>>>(Wq, Wh + 0 * WSZ, Wl + 0 * WSZ, NW);
    split_f32<<<NW / 4 / 256, 256>>>(Wk, Wh + 1 * WSZ, Wl + 1 * WSZ, NW);
    split_f32<<<NW / 4 / 256, 256>>>(Wv, Wh + 2 * WSZ, Wl + 2 * WSZ, NW);

    // QKV projections: 3-term. Q -> hi+lo; K,V -> hi only.
    dim3 g1(MTOT / 128, FDIM / 128, 1);
    gemm_mma<<<g1, 256, SMEM_SZ>>>(xh, xl, Wh + 0 * WSZ, Wl + 0 * WSZ, bq,
                                   Qh, Ql, nullptr, FDIM, FDIM, 1.0f, 3, 0, 0, 0, 0);
    gemm_mma<<<g1, 256, SMEM_SZ>>>(xh, xl, Wh + 1 * WSZ, Wl + 1 * WSZ, bk,
                                   Kh, nullptr, nullptr, FDIM, FDIM, 1.0f, 3, 1, 0, 0, 0);
    gemm_mma<<<g1, 256, SMEM_SZ>>>(xh, xl, Wh + 2 * WSZ, Wl + 2 * WSZ, bv,
                                   Vh, nullptr, nullptr, FDIM, FDIM, 1.0f, 3, 1, 0, 0, 0);

    // scores = Q @ K^T / 32 : 2-term (Qh,Ql vs Kh), fp32 out
    dim3 g2(SEQ / 128, SEQ / 128, BATCH);
    gemm_mma<<<g2, 256, SMEM_SZ>>>(Qh, Ql, Kh, nullptr, nullptr, nullptr, nullptr, S,
                                   SEQ, FDIM, 0.03125f, 2, 2,
                                   (long long)SEQ * FDIM, (long long)SEQ * FDIM,
                                   (long long)SEQ * SEQ);

    transpose_v<<<dim3(SEQ / 32, FDIM / 32, BATCH), dim3(32, 8)>>>(Vh, Vth);

    softmax_rows<<<BATCH * SEQ, 256>>>(S, Ph, Pl);

    // out = P @ Vt^T : 2-term (Ph,Pl vs Vth), fp32 out
    dim3 g3(SEQ / 128, FDIM / 128, BATCH);
    gemm_mma<<<g3, 256, SMEM_SZ>>>(Ph, Pl, Vth, nullptr, nullptr, nullptr, nullptr, out,
                                   FDIM, SEQ, 1.0f, 2, 2,
                                   (long long)SEQ * SEQ, (long long)FDIM * SEQ,
                                   (long long)SEQ * FDIM);
}

// round 7
// speedup vs baseline: 1.4592x; 1.1638x over previous
#include <cuda_runtime.h>
#include <cuda_fp16.h>
#include <cstdint>

#define FDIM 1024
#define BATCH 8
#define SEQ 2048
#define MTOT (BATCH * SEQ)   // 16384

#define LO_SCALE   1024.0f
#define INV_LO     (1.0f / 1024.0f)

// ---------------- scratch (__device__ globals) ----------------
__device__ __half g_xh[MTOT * FDIM], g_xl[MTOT * FDIM];
__device__ __half g_Wh[3][FDIM * FDIM];
__device__ __half g_Qh[MTOT * FDIM], g_Ql[MTOT * FDIM];
__device__ __half g_Kh[MTOT * FDIM];
__device__ __half g_Vh[MTOT * FDIM];
__device__ __half g_Vth[BATCH * FDIM * SEQ];
__device__ float  g_S[(size_t)BATCH * SEQ * SEQ];
__device__ __half g_Ph[(size_t)BATCH * SEQ * SEQ], g_Pl[(size_t)BATCH * SEQ * SEQ];

// ---------------- PTX helpers ----------------
__device__ __forceinline__ uint32_t smem_to_u32(const void* p) {
    uint32_t a;
    asm("{ .reg .u64 t; cvta.to.shared.u64 t, %1; cvt.u32.u64 %0, t; }" : "=r"(a) : "l"(p));
    return a;
}
__device__ __forceinline__ void cp_async16(uint32_t dst, const void* src) {
    asm volatile("cp.async.cg.shared.global [%0], [%1], 16;" :: "r"(dst), "l"(src));
}
#define CP_COMMIT() asm volatile("cp.async.commit_group;" ::: "memory")
#define CP_WAIT0()  asm volatile("cp.async.wait_group 0;" ::: "memory")
#define CP_WAIT1()  asm volatile("cp.async.wait_group 1;" ::: "memory")

__device__ __forceinline__ void ldm4(uint32_t (&r)[4], uint32_t addr) {
    asm volatile("ldmatrix.sync.aligned.m8n8.x4.shared.b16 {%0,%1,%2,%3}, [%4];"
                 : "=r"(r[0]), "=r"(r[1]), "=r"(r[2]), "=r"(r[3]) : "r"(addr));
}
// fp32-accum fp16 MMA (main product)
__device__ __forceinline__ void mma_f32(float (&d)[4], const uint32_t (&a)[4],
                                        uint32_t b0, uint32_t b1) {
    asm volatile("mma.sync.aligned.m16n8k16.row.col.f32.f16.f16.f32 "
                 "{%0,%1,%2,%3}, {%4,%5,%6,%7}, {%8,%9}, {%0,%1,%2,%3};"
                 : "+f"(d[0]), "+f"(d[1]), "+f"(d[2]), "+f"(d[3])
                 : "r"(a[0]), "r"(a[1]), "r"(a[2]), "r"(a[3]), "r"(b0), "r"(b1));
}
// fp16-accum fp16 MMA (correction term)
__device__ __forceinline__ void mma_f16(uint32_t (&d)[2], const uint32_t (&a)[4],
                                        uint32_t b0, uint32_t b1) {
    asm volatile("mma.sync.aligned.m16n8k16.row.col.f16.f16.f16.f16 "
                 "{%0,%1}, {%2,%3,%4,%5}, {%6,%7}, {%0,%1};"
                 : "+r"(d[0]), "+r"(d[1])
                 : "r"(a[0]), "r"(a[1]), "r"(a[2]), "r"(a[3]), "r"(b0), "r"(b1));
}

// ---------------- GEMM config ----------------
// CTA 128(m) x 128(n), BK=32, 8 warps (2m x 4n), warp tile 64x32.
// SMEM stage: Ah, Al, Bh tiles, 128 rows x 32 fp16 (64 B) padded to 80 B.
#define ROWPAD   80
#define TILE_B   (128 * ROWPAD)            // 10240
#define STAGE_B  (3 * TILE_B)              // 30720
#define NSTAGE   3
#define SMEM_SZ  (NSTAGE * STAGE_B)        // 92160

__device__ __forceinline__ void load_chunk(
    uint32_t st, int tid,
    const __half* Ah, const __half* Al, const __half* Bh,
    long long kofs, int Kd)
{
    #pragma unroll
    for (int i = 0; i < 2; i++) {
        int u = tid + i * 256;
        int row = u >> 2, seg = u & 3;
        long long go = (long long)row * Kd + kofs + seg * 8;
        uint32_t so = row * ROWPAD + seg * 16;
        cp_async16(st + so,              Ah + go);
        cp_async16(st + TILE_B + so,     Al + go);
        cp_async16(st + 2 * TILE_B + so, Bh + go);
    }
    CP_COMMIT();
}

// C(MxN) = alpha*(A @ B^T) [+bias].  A = Ah + Al/1024 (Al pre-scaled x1024), B = Bh.
// 2-term: Ah*Bh (f32 acc) + Al*Bh (f16 acc).
// omode 0: half hi+lo out (+bias). 1: half hi out (+bias). 2: fp32 out.
__global__ __launch_bounds__(256, 1) void gemm_mma(
    const __half* __restrict__ Ahi, const __half* __restrict__ Alo,
    const __half* __restrict__ Bhi,
    const float* __restrict__ bias,
    __half* __restrict__ outHi, __half* __restrict__ outLo,
    float* __restrict__ outF,
    int N, int Kd, float alpha, int omode,
    long long sA, long long sB, long long sC)
{
    extern __shared__ char smem[];
    const uint32_t smem0 = smem_to_u32(smem);
    const int tid = threadIdx.x;
    const int wid = tid >> 5;
    const int lane = tid & 31;
    const int z = blockIdx.z;
    const long long row0 = (long long)blockIdx.x * 128;
    const long long col0 = (long long)blockIdx.y * 128;

    const __half* Ah = Ahi + (long long)z * sA + row0 * Kd;
    const __half* Al = Alo + (long long)z * sA + row0 * Kd;
    const __half* Bh = Bhi + (long long)z * sB + col0 * Kd;

    const int warp_m0 = (wid >> 2) * 64;   // 0,64
    const int warp_n0 = (wid & 3) * 32;    // 0,32,64,96

    const uint32_t lmofs = (uint32_t)(lane & 15) * ROWPAD + (uint32_t)(lane >> 4) * 16;

    float acc[4][4][4];
    uint32_t accH[4][4][2];
    #pragma unroll
    for (int a = 0; a < 4; a++)
        #pragma unroll
        for (int b = 0; b < 4; b++) {
            accH[a][b][0] = 0u; accH[a][b][1] = 0u;
            #pragma unroll
            for (int cI = 0; cI < 4; cI++) acc[a][b][cI] = 0.0f;
        }

    const int NC = Kd >> 5;   // BK=32

    load_chunk(smem0, tid, Ah, Al, Bh, 0, Kd);
    load_chunk(smem0 + STAGE_B, tid, Ah, Al, Bh, 32, Kd);

    int stage = 0;
    for (int c = 0; c < NC; c++) {
        if (c + 1 < NC) CP_WAIT1(); else CP_WAIT0();
        __syncthreads();

        const uint32_t st = smem0 + stage * STAGE_B;
        const uint32_t tAh = st, tAl = st + TILE_B, tBh = st + 2 * TILE_B;

        #pragma unroll
        for (int ks = 0; ks < 2; ks++) {
            uint32_t ah[4][4], al[4][4], bh[2][4];
            #pragma unroll
            for (int g = 0; g < 4; g++) {
                uint32_t oa = (uint32_t)(warp_m0 + g * 16) * ROWPAD + ks * 32 + lmofs;
                ldm4(ah[g], tAh + oa);
                ldm4(al[g], tAl + oa);
            }
            #pragma unroll
            for (int g = 0; g < 2; g++) {
                uint32_t ob = (uint32_t)(warp_n0 + g * 16) * ROWPAD + ks * 32 + lmofs;
                ldm4(bh[g], tBh + ob);
            }
            // main: Ah * Bh  (fp32 accum)
            #pragma unroll
            for (int mf = 0; mf < 4; mf++)
                #pragma unroll
                for (int g = 0; g < 2; g++)
                    #pragma unroll
                    for (int p = 0; p < 2; p++)
                        mma_f32(acc[mf][g * 2 + p], ah[mf], bh[g][p], bh[g][p + 2]);
            // correction: Al' * Bh  (f16 accum)
            #pragma unroll
            for (int mf = 0; mf < 4; mf++)
                #pragma unroll
                for (int g = 0; g < 2; g++)
                    #pragma unroll
                    for (int p = 0; p < 2; p++)
                        mma_f16(accH[mf][g * 2 + p], al[mf], bh[g][p], bh[g][p + 2]);
        }

        if (c + 2 < NC) {
            int ns = stage + 2; if (ns >= NSTAGE) ns -= NSTAGE;
            load_chunk(smem0 + ns * STAGE_B, tid, Ah, Al, Bh,
                       (long long)(c + 2) * 32, Kd);
        }
        if (++stage == NSTAGE) stage = 0;
    }

    // ---- epilogue ----
    const int rbase = warp_m0 + (lane >> 2);
    const int cbase = warp_n0 + 2 * (lane & 3);
    #pragma unroll
    for (int mf = 0; mf < 4; mf++) {
        #pragma unroll
        for (int nf = 0; nf < 4; nf++) {
            #pragma unroll
            for (int h = 0; h < 2; h++) {
                long long r = row0 + rbase + mf * 16 + h * 8;
                long long cc = col0 + cbase + nf * 8;
                __half2 ch = *reinterpret_cast<const __half2*>(&accH[mf][nf][h]);
                float2 cf = __half22float2(ch);
                float f0 = (acc[mf][nf][h * 2 + 0] + cf.x * INV_LO) * alpha;
                float f1 = (acc[mf][nf][h * 2 + 1] + cf.y * INV_LO) * alpha;
                if (omode <= 1) {
                    f0 += bias[cc];
                    f1 += bias[cc + 1];
                    __half h0 = __float2half(f0);
                    __half h1 = __float2half(f1);
                    long long o = r * (long long)N + cc;
                    __half2 ph; ph.x = h0; ph.y = h1;
                    *(__half2*)(outHi + o) = ph;
                    if (omode == 0) {
                        __half2 pl;
                        pl.x = __float2half((f0 - __half2float(h0)) * LO_SCALE);
                        pl.y = __float2half((f1 - __half2float(h1)) * LO_SCALE);
                        *(__half2*)(outLo + o) = pl;
                    }
                } else {
                    long long o = (long long)z * sC + r * (long long)N + cc;
                    *(float2*)(outF + o) = make_float2(f0, f1);
                }
            }
        }
    }
}

// split fp32 -> hi fp16 (+ optional lo*1024 fp16)
__global__ __launch_bounds__(256) void split_f32(
    const float* __restrict__ src, __half* __restrict__ hi,
    __half* __restrict__ lo, int n)
{
    int i = (blockIdx.x * 256 + threadIdx.x) * 4;
    if (i >= n) return;
    float4 v = *(const float4*)(src + i);
    float f[4] = { v.x, v.y, v.z, v.w };
    __half h[4];
    #pragma unroll
    for (int k = 0; k < 4; k++) h[k] = __float2half(f[k]);
    __half2 h0; h0.x = h[0]; h0.y = h[1];
    __half2 h1; h1.x = h[2]; h1.y = h[3];
    *(__half2*)(hi + i) = h0; *(__half2*)(hi + i + 2) = h1;
    if (lo) {
        __half l[4];
        #pragma unroll
        for (int k = 0; k < 4; k++)
            l[k] = __float2half((f[k] - __half2float(h[k])) * LO_SCALE);
        __half2 l0; l0.x = l[0]; l0.y = l[1];
        __half2 l1; l1.x = l[2]; l1.y = l[3];
        *(__half2*)(lo + i) = l0; *(__half2*)(lo + i + 2) = l1;
    }
}

// Vt[b][d][s] = V[b*SEQ+s][d]  (hi only)
__global__ __launch_bounds__(256) void transpose_v(
    const __half* __restrict__ Vh, __half* __restrict__ Vth)
{
    __shared__ __half th[32][33];
    const int b = blockIdx.z;
    const int s0 = blockIdx.x * 32, d0 = blockIdx.y * 32;
    const int tx = threadIdx.x, ty = threadIdx.y;
    #pragma unroll
    for (int j = 0; j < 4; j++) {
        int r = ty + j * 8;
        th[r][tx] = Vh[(long long)(b * SEQ + s0 + r) * FDIM + d0 + tx];
    }
    __syncthreads();
    #pragma unroll
    for (int j = 0; j < 4; j++) {
        int r = ty + j * 8;
        Vth[(long long)(b * FDIM + d0 + r) * SEQ + s0 + tx] = th[tx][r];
    }
}

// row softmax: S fp32 -> P hi + lo*1024 fp16
__global__ __launch_bounds__(256) void softmax_rows(
    const float* __restrict__ S, __half* __restrict__ Ph, __half* __restrict__ Pl)
{
    __shared__ float red[256];
    const long long roff = (long long)blockIdx.x * SEQ;
    const float* p = S + roff;
    const int tid = threadIdx.x;

    float v[8];
    float mx = -1e30f;
    #pragma unroll
    for (int i = 0; i < 8; i++) { v[i] = p[tid + i * 256]; mx = fmaxf(mx, v[i]); }
    red[tid] = mx;
    __syncthreads();
    for (int s = 128; s > 0; s >>= 1) {
        if (tid < s) red[tid] = fmaxf(red[tid], red[tid + s]);
        __syncthreads();
    }
    mx = red[0];
    __syncthreads();

    float sum = 0.0f;
    #pragma unroll
    for (int i = 0; i < 8; i++) { v[i] = __expf(v[i] - mx); sum += v[i]; }
    red[tid] = sum;
    __syncthreads();
    for (int s = 128; s > 0; s >>= 1) {
        if (tid < s) red[tid] += red[tid + s];
        __syncthreads();
    }
    float inv = 1.0f / red[0];

    #pragma unroll
    for (int i = 0; i < 8; i++) {
        float w = v[i] * inv;
        __half h = __float2half(w);
        Ph[roff + tid + i * 256] = h;
        Pl[roff + tid + i * 256] = __float2half((w - __half2float(h)) * LO_SCALE);
    }
}

extern "C" void kernel_launch(void* const* d_in, const int* in_sizes, int n_in,
                              void* d_out, int out_size)
{
    const float* x  = (const float*)d_in[0];
    const float* Wq = (const float*)d_in[1];
    const float* bq = (const float*)d_in[2];
    const float* Wk = (const float*)d_in[3];
    const float* bk = (const float*)d_in[4];
    const float* Wv = (const float*)d_in[5];
    const float* bv = (const float*)d_in[6];
    float* out = (float*)d_out;

    cudaFuncSetAttribute(gemm_mma, cudaFuncAttributeMaxDynamicSharedMemorySize, SMEM_SZ);

    __half *xh, *xl, *Wh, *Qh, *Ql, *Kh, *Vh, *Vth, *Ph, *Pl;
    float* S;
    cudaGetSymbolAddress((void**)&xh, g_xh);   cudaGetSymbolAddress((void**)&xl, g_xl);
    cudaGetSymbolAddress((void**)&Wh, g_Wh);
    cudaGetSymbolAddress((void**)&Qh, g_Qh);   cudaGetSymbolAddress((void**)&Ql, g_Ql);
    cudaGetSymbolAddress((void**)&Kh, g_Kh);
    cudaGetSymbolAddress((void**)&Vh, g_Vh);
    cudaGetSymbolAddress((void**)&Vth, g_Vth);
    cudaGetSymbolAddress((void**)&Ph, g_Ph);   cudaGetSymbolAddress((void**)&Pl, g_Pl);
    cudaGetSymbolAddress((void**)&S, g_S);

    const int NX = MTOT * FDIM;
    const int NW = FDIM * FDIM;
    const long long WSZ = (long long)FDIM * FDIM;

    split_f32<<<NX / 4 / 256, 256>>>(x, xh, xl, NX);
    split_f32<<<NW / 4 / 256, 256>>>(Wq, Wh + 0 * WSZ, nullptr, NW);
    split_f32<<<NW / 4 / 256, 256>>>(Wk, Wh + 1 * WSZ, nullptr, NW);
    split_f32<<<NW / 4 / 256, 256>>>(Wv, Wh + 2 * WSZ, nullptr, NW);

    // QKV projections: 2-term (xh,xl vs Wh). Q -> hi+lo; K,V -> hi only.
    dim3 g1(MTOT / 128, FDIM / 128, 1);
    gemm_mma<<<g1, 256, SMEM_SZ>>>(xh, xl, Wh + 0 * WSZ, bq,
                                   Qh, Ql, nullptr, FDIM, FDIM, 1.0f, 0, 0, 0, 0);
    gemm_mma<<<g1, 256, SMEM_SZ>>>(xh, xl, Wh + 1 * WSZ, bk,
                                   Kh, nullptr, nullptr, FDIM, FDIM, 1.0f, 1, 0, 0, 0);
    gemm_mma<<<g1, 256, SMEM_SZ>>>(xh, xl, Wh + 2 * WSZ, bv,
                                   Vh, nullptr, nullptr, FDIM, FDIM, 1.0f, 1, 0, 0, 0);

    // scores = Q @ K^T / 32 : 2-term (Qh,Ql vs Kh), fp32 out
    dim3 g2(SEQ / 128, SEQ / 128, BATCH);
    gemm_mma<<<g2, 256, SMEM_SZ>>>(Qh, Ql, Kh, nullptr, nullptr, nullptr, S,
                                   SEQ, FDIM, 0.03125f, 2,
                                   (long long)SEQ * FDIM, (long long)SEQ * FDIM,
                                   (long long)SEQ * SEQ);

    transpose_v<<<dim3(SEQ / 32, FDIM / 32, BATCH), dim3(32, 8)>>>(Vh, Vth);

    softmax_rows<<<BATCH * SEQ, 256>>>(S, Ph, Pl);

    // out = P @ Vt^T : 2-term (Ph,Pl vs Vth), fp32 out
    dim3 g3(SEQ / 128, FDIM / 128, BATCH);
    gemm_mma<<<g3, 256, SMEM_SZ>>>(Ph, Pl, Vth, nullptr, nullptr, nullptr, out,
                                   FDIM, SEQ, 1.0f, 2,
                                   (long long)SEQ * SEQ, (long long)FDIM * SEQ,
                                   (long long)SEQ * FDIM);
}

// round 8
// speedup vs baseline: 2.8357x; 1.9433x over previous
#include <cuda_runtime.h>
#include <cuda_fp16.h>
#include <cstdint>

#define FDIM 1024
#define BATCH 8
#define SEQ 2048
#define MTOT (BATCH * SEQ)   // 16384

// ---------------- scratch (__device__ globals) ----------------
__device__ __half g_xh[MTOT * FDIM];
__device__ __half g_Wh[3][FDIM * FDIM];
__device__ __half g_Qh[MTOT * FDIM];
__device__ __half g_Kh[MTOT * FDIM];
__device__ __half g_Vh[MTOT * FDIM];
__device__ __half g_Vth[BATCH * FDIM * SEQ];
__device__ float  g_S[(size_t)BATCH * SEQ * SEQ];
__device__ __half g_Ph[(size_t)BATCH * SEQ * SEQ];

// ---------------- PTX helpers ----------------
__device__ __forceinline__ uint32_t smem_to_u32(const void* p) {
    uint32_t a;
    asm("{ .reg .u64 t; cvta.to.shared.u64 t, %1; cvt.u32.u64 %0, t; }" : "=r"(a) : "l"(p));
    return a;
}
__device__ __forceinline__ void cp_async16(uint32_t dst, const void* src) {
    asm volatile("cp.async.cg.shared.global [%0], [%1], 16;" :: "r"(dst), "l"(src));
}
#define CP_COMMIT() asm volatile("cp.async.commit_group;" ::: "memory")
#define CP_WAIT0()  asm volatile("cp.async.wait_group 0;" ::: "memory")
#define CP_WAIT1()  asm volatile("cp.async.wait_group 1;" ::: "memory")

__device__ __forceinline__ void ldm4(uint32_t (&r)[4], uint32_t addr) {
    asm volatile("ldmatrix.sync.aligned.m8n8.x4.shared.b16 {%0,%1,%2,%3}, [%4];"
                 : "=r"(r[0]), "=r"(r[1]), "=r"(r[2]), "=r"(r[3]) : "r"(addr));
}
__device__ __forceinline__ void mma_f32(float (&d)[4], const uint32_t (&a)[4],
                                        uint32_t b0, uint32_t b1) {
    asm volatile("mma.sync.aligned.m16n8k16.row.col.f32.f16.f16.f32 "
                 "{%0,%1,%2,%3}, {%4,%5,%6,%7}, {%8,%9}, {%0,%1,%2,%3};"
                 : "+f"(d[0]), "+f"(d[1]), "+f"(d[2]), "+f"(d[3])
                 : "r"(a[0]), "r"(a[1]), "r"(a[2]), "r"(a[3]), "r"(b0), "r"(b1));
}

// ---------------- GEMM config ----------------
// CTA 128(m) x 128(n), BK=32, 8 warps (2m x 4n), warp tile 64x32.
// SMEM stage: A, B tiles, 128 rows x 32 fp16 (64 B) padded to 80 B.
#define ROWPAD   80
#define TILE_B   (128 * ROWPAD)            // 10240
#define STAGE_B  (2 * TILE_B)              // 20480
#define NSTAGE   3
#define SMEM_SZ  (NSTAGE * STAGE_B)        // 61440

__device__ __forceinline__ void load_chunk(
    uint32_t st, int tid,
    const __half* A, const __half* B, long long kofs, int Kd)
{
    #pragma unroll
    for (int i = 0; i < 2; i++) {
        int u = tid + i * 256;
        int row = u >> 2, seg = u & 3;
        long long go = (long long)row * Kd + kofs + seg * 8;
        uint32_t so = row * ROWPAD + seg * 16;
        cp_async16(st + so,          A + go);
        cp_async16(st + TILE_B + so, B + go);
    }
    CP_COMMIT();
}

// C(MxN) = alpha*(A @ B^T) [+bias]; pure fp16 MMA, fp32 accum.
// omode 0: half out (+bias). else: fp32 out (batch stride sC).
__global__ __launch_bounds__(256) void gemm_mma(
    const __half* __restrict__ Ag, const __half* __restrict__ Bg,
    const float* __restrict__ bias,
    __half* __restrict__ outH, float* __restrict__ outF,
    int N, int Kd, float alpha, int omode,
    long long sA, long long sB, long long sC)
{
    extern __shared__ char smem[];
    const uint32_t smem0 = smem_to_u32(smem);
    const int tid = threadIdx.x;
    const int wid = tid >> 5;
    const int lane = tid & 31;
    const int z = blockIdx.z;
    const long long row0 = (long long)blockIdx.x * 128;
    const long long col0 = (long long)blockIdx.y * 128;

    const __half* A = Ag + (long long)z * sA + row0 * Kd;
    const __half* B = Bg + (long long)z * sB + col0 * Kd;

    const int warp_m0 = (wid >> 2) * 64;   // 0,64
    const int warp_n0 = (wid & 3) * 32;    // 0,32,64,96

    const uint32_t lmofs = (uint32_t)(lane & 15) * ROWPAD + (uint32_t)(lane >> 4) * 16;

    float acc[4][4][4];
    #pragma unroll
    for (int a = 0; a < 4; a++)
        #pragma unroll
        for (int b = 0; b < 4; b++)
            #pragma unroll
            for (int cI = 0; cI < 4; cI++) acc[a][b][cI] = 0.0f;

    const int NC = Kd >> 5;   // BK=32

    load_chunk(smem0, tid, A, B, 0, Kd);
    load_chunk(smem0 + STAGE_B, tid, A, B, 32, Kd);

    int stage = 0;
    for (int c = 0; c < NC; c++) {
        if (c + 1 < NC) CP_WAIT1(); else CP_WAIT0();
        __syncthreads();

        const uint32_t st = smem0 + stage * STAGE_B;
        const uint32_t tA = st, tB = st + TILE_B;

        #pragma unroll
        for (int ks = 0; ks < 2; ks++) {
            uint32_t af[4][4], bf[2][4];
            #pragma unroll
            for (int g = 0; g < 4; g++) {
                uint32_t oa = (uint32_t)(warp_m0 + g * 16) * ROWPAD + ks * 32 + lmofs;
                ldm4(af[g], tA + oa);
            }
            #pragma unroll
            for (int g = 0; g < 2; g++) {
                uint32_t ob = (uint32_t)(warp_n0 + g * 16) * ROWPAD + ks * 32 + lmofs;
                ldm4(bf[g], tB + ob);
            }
            #pragma unroll
            for (int mf = 0; mf < 4; mf++)
                #pragma unroll
                for (int g = 0; g < 2; g++)
                    #pragma unroll
                    for (int p = 0; p < 2; p++)
                        mma_f32(acc[mf][g * 2 + p], af[mf], bf[g][p], bf[g][p + 2]);
        }

        if (c + 2 < NC) {
            int ns = stage + 2; if (ns >= NSTAGE) ns -= NSTAGE;
            load_chunk(smem0 + ns * STAGE_B, tid, A, B, (long long)(c + 2) * 32, Kd);
        }
        if (++stage == NSTAGE) stage = 0;
    }

    // ---- epilogue ----
    const int rbase = warp_m0 + (lane >> 2);
    const int cbase = warp_n0 + 2 * (lane & 3);
    #pragma unroll
    for (int mf = 0; mf < 4; mf++) {
        #pragma unroll
        for (int nf = 0; nf < 4; nf++) {
            #pragma unroll
            for (int h = 0; h < 2; h++) {
                long long r = row0 + rbase + mf * 16 + h * 8;
                long long cc = col0 + cbase + nf * 8;
                float f0 = acc[mf][nf][h * 2 + 0] * alpha;
                float f1 = acc[mf][nf][h * 2 + 1] * alpha;
                if (omode == 0) {
                    f0 += bias[cc];
                    f1 += bias[cc + 1];
                    __half2 ph; ph.x = __float2half(f0); ph.y = __float2half(f1);
                    *(__half2*)(outH + r * (long long)N + cc) = ph;
                } else {
                    long long o = (long long)z * sC + r * (long long)N + cc;
                    *(float2*)(outF + o) = make_float2(f0, f1);
                }
            }
        }
    }
}

// fp32 -> fp16
__global__ __launch_bounds__(256) void to_half(
    const float* __restrict__ src, __half* __restrict__ dst, int n)
{
    int i = (blockIdx.x * 256 + threadIdx.x) * 4;
    if (i >= n) return;
    float4 v = *(const float4*)(src + i);
    __half2 h0; h0.x = __float2half(v.x); h0.y = __float2half(v.y);
    __half2 h1; h1.x = __float2half(v.z); h1.y = __float2half(v.w);
    *(__half2*)(dst + i) = h0; *(__half2*)(dst + i + 2) = h1;
}

// Vt[b][d][s] = V[b*SEQ+s][d]
__global__ __launch_bounds__(256) void transpose_v(
    const __half* __restrict__ Vh, __half* __restrict__ Vth)
{
    __shared__ __half th[32][33];
    const int b = blockIdx.z;
    const int s0 = blockIdx.x * 32, d0 = blockIdx.y * 32;
    const int tx = threadIdx.x, ty = threadIdx.y;
    #pragma unroll
    for (int j = 0; j < 4; j++) {
        int r = ty + j * 8;
        th[r][tx] = Vh[(long long)(b * SEQ + s0 + r) * FDIM + d0 + tx];
    }
    __syncthreads();
    #pragma unroll
    for (int j = 0; j < 4; j++) {
        int r = ty + j * 8;
        Vth[(long long)(b * FDIM + d0 + r) * SEQ + s0 + tx] = th[tx][r];
    }
}

// row softmax: S fp32 -> P fp16
__global__ __launch_bounds__(256) void softmax_rows(
    const float* __restrict__ S, __half* __restrict__ Ph)
{
    __shared__ float red[256];
    const long long roff = (long long)blockIdx.x * SEQ;
    const float* p = S + roff;
    const int tid = threadIdx.x;

    float v[8];
    float mx = -1e30f;
    #pragma unroll
    for (int i = 0; i < 8; i++) { v[i] = p[tid + i * 256]; mx = fmaxf(mx, v[i]); }
    red[tid] = mx;
    __syncthreads();
    for (int s = 128; s > 0; s >>= 1) {
        if (tid < s) red[tid] = fmaxf(red[tid], red[tid + s]);
        __syncthreads();
    }
    mx = red[0];
    __syncthreads();

    float sum = 0.0f;
    #pragma unroll
    for (int i = 0; i < 8; i++) { v[i] = __expf(v[i] - mx); sum += v[i]; }
    red[tid] = sum;
    __syncthreads();
    for (int s = 128; s > 0; s >>= 1) {
        if (tid < s) red[tid] += red[tid + s];
        __syncthreads();
    }
    float inv = 1.0f / red[0];

    #pragma unroll
    for (int i = 0; i < 8; i++)
        Ph[roff + tid + i * 256] = __float2half(v[i] * inv);
}

extern "C" void kernel_launch(void* const* d_in, const int* in_sizes, int n_in,
                              void* d_out, int out_size)
{
    const float* x  = (const float*)d_in[0];
    const float* Wq = (const float*)d_in[1];
    const float* bq = (const float*)d_in[2];
    const float* Wk = (const float*)d_in[3];
    const float* bk = (const float*)d_in[4];
    const float* Wv = (const float*)d_in[5];
    const float* bv = (const float*)d_in[6];
    float* out = (float*)d_out;

    cudaFuncSetAttribute(gemm_mma, cudaFuncAttributeMaxDynamicSharedMemorySize, SMEM_SZ);

    __half *xh, *Wh, *Qh, *Kh, *Vh, *Vth, *Ph;
    float* S;
    cudaGetSymbolAddress((void**)&xh, g_xh);
    cudaGetSymbolAddress((void**)&Wh, g_Wh);
    cudaGetSymbolAddress((void**)&Qh, g_Qh);
    cudaGetSymbolAddress((void**)&Kh, g_Kh);
    cudaGetSymbolAddress((void**)&Vh, g_Vh);
    cudaGetSymbolAddress((void**)&Vth, g_Vth);
    cudaGetSymbolAddress((void**)&Ph, g_Ph);
    cudaGetSymbolAddress((void**)&S, g_S);

    const int NX = MTOT * FDIM;
    const int NW = FDIM * FDIM;
    const long long WSZ = (long long)FDIM * FDIM;

    to_half<<<NX / 4 / 256, 256>>>(x, xh, NX);
    to_half<<<NW / 4 / 256, 256>>>(Wq, Wh + 0 * WSZ, NW);
    to_half<<<NW / 4 / 256, 256>>>(Wk, Wh + 1 * WSZ, NW);
    to_half<<<NW / 4 / 256, 256>>>(Wv, Wh + 2 * WSZ, NW);

    // QKV projections (fp16 out + bias)
    dim3 g1(MTOT / 128, FDIM / 128, 1);
    gemm_mma<<<g1, 256, SMEM_SZ>>>(xh, Wh + 0 * WSZ, bq, Qh, nullptr,
                                   FDIM, FDIM, 1.0f, 0, 0, 0, 0);
    gemm_mma<<<g1, 256, SMEM_SZ>>>(xh, Wh + 1 * WSZ, bk, Kh, nullptr,
                                   FDIM, FDIM, 1.0f, 0, 0, 0, 0);
    gemm_mma<<<g1, 256, SMEM_SZ>>>(xh, Wh + 2 * WSZ, bv, Vh, nullptr,
                                   FDIM, FDIM, 1.0f, 0, 0, 0, 0);

    // scores = Q @ K^T / 32  (fp32 out)
    dim3 g2(SEQ / 128, SEQ / 128, BATCH);
    gemm_mma<<<g2, 256, SMEM_SZ>>>(Qh, Kh, nullptr, nullptr, S,
                                   SEQ, FDIM, 0.03125f, 1,
                                   (long long)SEQ * FDIM, (long long)SEQ * FDIM,
                                   (long long)SEQ * SEQ);

    transpose_v<<<dim3(SEQ / 32, FDIM / 32, BATCH), dim3(32, 8)>>>(Vh, Vth);

    softmax_rows<<<BATCH * SEQ, 256>>>(S, Ph);

    // out = P @ Vt^T  (fp32 out)
    dim3 g3(SEQ / 128, FDIM / 128, BATCH);
    gemm_mma<<<g3, 256, SMEM_SZ>>>(Ph, Vth, nullptr, nullptr, out,
                                   FDIM, SEQ, 1.0f, 1,
                                   (long long)SEQ * SEQ, (long long)FDIM * SEQ,
                                   (long long)SEQ * FDIM);
}